// round 1
// baseline (speedup 1.0000x reference)
#include <cuda_runtime.h>
#include <cstdint>

// MXFP6 quant-dequant, straight-through forward => output = dequant(quant(x)).
// x: [4096, 8192] fp32, blocks of 32 contiguous elements share a scale.
// Per block: m = max(|x|, 1e-8); e = floor(log2(m)); scale = 2^e;
//            q = clip(round(x/scale*15), -15, 15); out = (q/15)*scale.
//
// One float4 per thread; 8 consecutive lanes = one 32-elem block.
// Max-reduce across the aligned 8-lane group with 3 shfl_xor ops.

__global__ __launch_bounds__(256, 8)
void mxfp6_qdq_kernel(const float* __restrict__ x,
                      float* __restrict__ out,
                      int n4)
{
    int i = blockIdx.x * blockDim.x + threadIdx.x;
    if (i >= n4) return;

    float4 v = reinterpret_cast<const float4*>(x)[i];

    float m = fmaxf(fmaxf(fabsf(v.x), fabsf(v.y)),
                    fmaxf(fabsf(v.z), fabsf(v.w)));

    // reduce max over the 8-lane group covering one 32-element block
    m = fmaxf(m, __shfl_xor_sync(0xffffffffu, m, 1));
    m = fmaxf(m, __shfl_xor_sync(0xffffffffu, m, 2));
    m = fmaxf(m, __shfl_xor_sync(0xffffffffu, m, 4));

    m = fmaxf(m, 1e-8f);

    // exact floor(log2(m)) for normal m, and exact power-of-two scales
    int e = (__float_as_int(m) >> 23) - 127;
    float scale     = __int_as_float((e + 127) << 23);
    float inv_scale = __int_as_float((127 - e) << 23);

    const float M = 15.0f;
    const float invM = 1.0f / 15.0f;

    // q = clip(rint(x * inv_scale * 15), -15, 15); out = (q*invM)*scale
    float qx = fminf(fmaxf(rintf(v.x * inv_scale * M), -M), M);
    float qy = fminf(fmaxf(rintf(v.y * inv_scale * M), -M), M);
    float qz = fminf(fmaxf(rintf(v.z * inv_scale * M), -M), M);
    float qw = fminf(fmaxf(rintf(v.w * inv_scale * M), -M), M);

    float4 o;
    o.x = (qx * invM) * scale;
    o.y = (qy * invM) * scale;
    o.z = (qz * invM) * scale;
    o.w = (qw * invM) * scale;

    reinterpret_cast<float4*>(out)[i] = o;
}

extern "C" void kernel_launch(void* const* d_in, const int* in_sizes, int n_in,
                              void* d_out, int out_size)
{
    const float* x = (const float*)d_in[0];
    float* out = (float*)d_out;
    int n = in_sizes[0];            // 33,554,432
    int n4 = n >> 2;                // 8,388,608 float4s
    int threads = 256;
    int blocks = (n4 + threads - 1) / threads;
    mxfp6_qdq_kernel<<<blocks, threads>>>(x, out, n4);
}

// round 2
// speedup vs baseline: 1.1209x; 1.1209x over previous
#include <cuda_runtime.h>
#include <cstdint>

// MXFP6 quant-dequant, straight-through forward => output = dequant(quant(x)).
// Blocks of 32 contiguous floats share a power-of-two scale.
//
// Layout: one float4 per lane per item; 8 consecutive lanes = one 32-elem
// block; 3x shfl_xor max-reduce within the aligned 8-lane group.
// ITEMS=4 independent items per thread -> MLP=4 loads in flight and four
// independent shfl chains to hide the ~26-cycle SHFL latency.

#define ITEMS 4

__global__ __launch_bounds__(256, 6)
void mxfp6_qdq_kernel(const float* __restrict__ x,
                      float* __restrict__ out,
                      int n4)
{
    const int base = blockIdx.x * (blockDim.x * ITEMS) + threadIdx.x;

    float4 v[ITEMS];
    bool ok[ITEMS];

    // Batch all loads first (independent -> 4 LDG.128 in flight)
    #pragma unroll
    for (int k = 0; k < ITEMS; k++) {
        int idx = base + k * 256;
        ok[k] = idx < n4;
        if (ok[k]) {
            v[k] = __ldcs(reinterpret_cast<const float4*>(x) + idx);
        }
    }

    // Local per-item max
    float m[ITEMS];
    #pragma unroll
    for (int k = 0; k < ITEMS; k++) {
        m[k] = fmaxf(fmaxf(fabsf(v[k].x), fabsf(v[k].y)),
                     fmaxf(fabsf(v[k].z), fabsf(v[k].w)));
    }

    // Four independent 3-step shfl chains; interleave to hide latency
    #pragma unroll
    for (int s = 1; s <= 4; s <<= 1) {
        #pragma unroll
        for (int k = 0; k < ITEMS; k++) {
            m[k] = fmaxf(m[k], __shfl_xor_sync(0xffffffffu, m[k], s));
        }
    }

    const float M = 15.0f;
    const float invM = 1.0f / 15.0f;

    #pragma unroll
    for (int k = 0; k < ITEMS; k++) {
        float mm = fmaxf(m[k], 1e-8f);
        // exact floor(log2) via exponent field; exact power-of-two scales
        int e = (__float_as_int(mm) >> 23) - 127;
        float scale     = __int_as_float((e + 127) << 23);
        float inv_scale = __int_as_float((127 - e) << 23);

        float qx = fminf(fmaxf(rintf(v[k].x * inv_scale * M), -M), M);
        float qy = fminf(fmaxf(rintf(v[k].y * inv_scale * M), -M), M);
        float qz = fminf(fmaxf(rintf(v[k].z * inv_scale * M), -M), M);
        float qw = fminf(fmaxf(rintf(v[k].w * inv_scale * M), -M), M);

        float4 o;
        o.x = (qx * invM) * scale;
        o.y = (qy * invM) * scale;
        o.z = (qz * invM) * scale;
        o.w = (qw * invM) * scale;

        if (ok[k]) {
            int idx = base + k * 256;
            __stcs(reinterpret_cast<float4*>(out) + idx, o);
        }
    }
}

extern "C" void kernel_launch(void* const* d_in, const int* in_sizes, int n_in,
                              void* d_out, int out_size)
{
    const float* x = (const float*)d_in[0];
    float* out = (float*)d_out;
    int n = in_sizes[0];             // 33,554,432
    int n4 = n >> 2;                 // 8,388,608 float4s
    const int threads = 256;
    int blocks = (n4 + threads * ITEMS - 1) / (threads * ITEMS);  // 8192
    mxfp6_qdq_kernel<<<blocks, threads>>>(x, out, n4);
}

// round 3
// speedup vs baseline: 1.1392x; 1.0163x over previous
#include <cuda_runtime.h>
#include <cstdint>

// MXFP6 quant-dequant, straight-through forward => output = dequant(quant(x)).
// Blocks of 32 contiguous floats share a power-of-two scale = 2^floor(log2(max|x|, clamped 1e-8)).
//
// Trick: only the EXPONENT BYTE of the block max matters. Exponent of max ==
// max of exponent fields, and the 1e-8 clamp == byte-clamp at field 100.
// So we pack the 4 items' local exponent bytes into one u32 and reduce the
// 8-lane group with 3 SHFL + __vmaxu4 (instead of 12 scalar float shuffles).

#define ITEMS 4

__device__ __forceinline__ float4 qdq4(float4 v, float scale, float inv_scale)
{
    const float M = 15.0f;
    const float invM = 1.0f / 15.0f;
    float4 o;
    o.x = (fminf(fmaxf(rintf(v.x * inv_scale * M), -M), M) * invM) * scale;
    o.y = (fminf(fmaxf(rintf(v.y * inv_scale * M), -M), M) * invM) * scale;
    o.z = (fminf(fmaxf(rintf(v.z * inv_scale * M), -M), M) * invM) * scale;
    o.w = (fminf(fmaxf(rintf(v.w * inv_scale * M), -M), M) * invM) * scale;
    return o;
}

__global__ __launch_bounds__(256, 6)
void mxfp6_qdq_kernel(const float* __restrict__ x,
                      float* __restrict__ out,
                      int n4)
{
    const int base = blockIdx.x * (blockDim.x * ITEMS) + threadIdx.x;

    float4 v[ITEMS];

    const bool full = (base + (ITEMS - 1) * 256) < n4;

    if (full) {
        #pragma unroll
        for (int k = 0; k < ITEMS; k++)
            v[k] = __ldcs(reinterpret_cast<const float4*>(x) + base + k * 256);
    } else {
        #pragma unroll
        for (int k = 0; k < ITEMS; k++) {
            int idx = base + k * 256;
            if (idx < n4) v[k] = __ldcs(reinterpret_cast<const float4*>(x) + idx);
            else          v[k] = make_float4(0.f, 0.f, 0.f, 0.f);
        }
    }

    // Per-item local max of |.| (fabs is a free operand modifier on FMNMX)
    unsigned s[ITEMS];
    #pragma unroll
    for (int k = 0; k < ITEMS; k++) {
        float m = fmaxf(fmaxf(fabsf(v[k].x), fabsf(v[k].y)),
                        fmaxf(fabsf(v[k].z), fabsf(v[k].w)));
        s[k] = __float_as_uint(m) << 1;   // top byte == exponent field
    }

    // Pack top bytes of s0..s3 into one word: byte k = exponent of item k
    unsigned lo = __byte_perm(s[0], s[1], 0x0073);  // b0=s0.top, b1=s1.top
    unsigned hi = __byte_perm(s[2], s[3], 0x0073);  // b0=s2.top, b1=s3.top
    unsigned w  = __byte_perm(lo, hi, 0x5410);      // b0,b1,b2,b3

    // SIMD byte-max across the 8-lane group (one 32-elem block per item)
    w = __vmaxu4(w, __shfl_xor_sync(0xffffffffu, w, 1));
    w = __vmaxu4(w, __shfl_xor_sync(0xffffffffu, w, 2));
    w = __vmaxu4(w, __shfl_xor_sync(0xffffffffu, w, 4));

    // 1e-8 clamp == exponent-field clamp at 100 (0x64), all 4 blocks at once
    w = __vmaxu4(w, 0x64646464u);

    if (full) {
        #pragma unroll
        for (int k = 0; k < ITEMS; k++) {
            unsigned e = __byte_perm(w, 0, k);            // extract byte k
            float scale     = __int_as_float((int)(e << 23));
            float inv_scale = __int_as_float((int)((254u - e) << 23));
            __stcs(reinterpret_cast<float4*>(out) + base + k * 256,
                   qdq4(v[k], scale, inv_scale));
        }
    } else {
        #pragma unroll
        for (int k = 0; k < ITEMS; k++) {
            int idx = base + k * 256;
            if (idx < n4) {
                unsigned e = __byte_perm(w, 0, k);
                float scale     = __int_as_float((int)(e << 23));
                float inv_scale = __int_as_float((int)((254u - e) << 23));
                __stcs(reinterpret_cast<float4*>(out) + idx,
                       qdq4(v[k], scale, inv_scale));
            }
        }
    }
}

extern "C" void kernel_launch(void* const* d_in, const int* in_sizes, int n_in,
                              void* d_out, int out_size)
{
    const float* x = (const float*)d_in[0];
    float* out = (float*)d_out;
    int n = in_sizes[0];             // 33,554,432
    int n4 = n >> 2;                 // 8,388,608 float4s
    const int threads = 256;
    int blocks = (n4 + threads * ITEMS - 1) / (threads * ITEMS);  // 8192
    mxfp6_qdq_kernel<<<blocks, threads>>>(x, out, n4);
}

// round 4
// speedup vs baseline: 1.1794x; 1.0353x over previous
#include <cuda_runtime.h>
#include <cstdint>

// MXFP6 quant-dequant, straight-through forward => output = dequant(quant(x)).
// Blocks of 32 contiguous floats share a power-of-two scale = 2^floor(log2(max|x|, clamp 1e-8)).
//
// Exponent-byte trick: only the exponent field of the block max matters.
// Pack 4 items' exponent bytes per u32; reduce the 8-lane group with
// 3 SHFL + __vmaxu4 per packed word. ITEMS=8 -> 8 LDG.128 in flight per
// thread (131KB/SM outstanding) to cover ~577cy DRAM latency.

#define ITEMS 8

__device__ __forceinline__ float4 qdq4(float4 v, float scale, float inv_scale)
{
    const float M = 15.0f;
    const float invM = 1.0f / 15.0f;
    float4 o;
    o.x = (fminf(fmaxf(rintf(v.x * inv_scale * M), -M), M) * invM) * scale;
    o.y = (fminf(fmaxf(rintf(v.y * inv_scale * M), -M), M) * invM) * scale;
    o.z = (fminf(fmaxf(rintf(v.z * inv_scale * M), -M), M) * invM) * scale;
    o.w = (fminf(fmaxf(rintf(v.w * inv_scale * M), -M), M) * invM) * scale;
    return o;
}

__global__ __launch_bounds__(256, 4)
void mxfp6_qdq_kernel(const float* __restrict__ x,
                      float* __restrict__ out,
                      int n4)
{
    const int base = blockIdx.x * (blockDim.x * ITEMS) + threadIdx.x;

    float4 v[ITEMS];

    const bool full = (base + (ITEMS - 1) * 256) < n4;

    if (full) {
        #pragma unroll
        for (int k = 0; k < ITEMS; k++)
            v[k] = __ldcs(reinterpret_cast<const float4*>(x) + base + k * 256);
    } else {
        #pragma unroll
        for (int k = 0; k < ITEMS; k++) {
            int idx = base + k * 256;
            if (idx < n4) v[k] = __ldcs(reinterpret_cast<const float4*>(x) + idx);
            else          v[k] = make_float4(0.f, 0.f, 0.f, 0.f);
        }
    }

    // Per-item local max of |.|; keep only the exponent byte (bits<<1 top byte)
    unsigned s[ITEMS];
    #pragma unroll
    for (int k = 0; k < ITEMS; k++) {
        float m = fmaxf(fmaxf(fabsf(v[k].x), fabsf(v[k].y)),
                        fmaxf(fabsf(v[k].z), fabsf(v[k].w)));
        s[k] = __float_as_uint(m) << 1;
    }

    // Pack exponent bytes: w0 = items 0..3, w1 = items 4..7
    unsigned w0, w1;
    {
        unsigned lo = __byte_perm(s[0], s[1], 0x0073);
        unsigned hi = __byte_perm(s[2], s[3], 0x0073);
        w0 = __byte_perm(lo, hi, 0x5410);
        lo = __byte_perm(s[4], s[5], 0x0073);
        hi = __byte_perm(s[6], s[7], 0x0073);
        w1 = __byte_perm(lo, hi, 0x5410);
    }

    // Two interleaved 3-step SIMD byte-max reductions over the 8-lane group
    #pragma unroll
    for (int st = 1; st <= 4; st <<= 1) {
        unsigned t0 = __shfl_xor_sync(0xffffffffu, w0, st);
        unsigned t1 = __shfl_xor_sync(0xffffffffu, w1, st);
        w0 = __vmaxu4(w0, t0);
        w1 = __vmaxu4(w1, t1);
    }

    // 1e-8 clamp == exponent-field clamp at 100 (0x64)
    w0 = __vmaxu4(w0, 0x64646464u);
    w1 = __vmaxu4(w1, 0x64646464u);

    if (full) {
        #pragma unroll
        for (int k = 0; k < ITEMS; k++) {
            unsigned e = __byte_perm(k < 4 ? w0 : w1, 0, k & 3);
            float scale     = __int_as_float((int)(e << 23));
            float inv_scale = __int_as_float((int)((254u - e) << 23));
            __stcs(reinterpret_cast<float4*>(out) + base + k * 256,
                   qdq4(v[k], scale, inv_scale));
        }
    } else {
        #pragma unroll
        for (int k = 0; k < ITEMS; k++) {
            int idx = base + k * 256;
            if (idx < n4) {
                unsigned e = __byte_perm(k < 4 ? w0 : w1, 0, k & 3);
                float scale     = __int_as_float((int)(e << 23));
                float inv_scale = __int_as_float((int)((254u - e) << 23));
                __stcs(reinterpret_cast<float4*>(out) + idx,
                       qdq4(v[k], scale, inv_scale));
            }
        }
    }
}

extern "C" void kernel_launch(void* const* d_in, const int* in_sizes, int n_in,
                              void* d_out, int out_size)
{
    const float* x = (const float*)d_in[0];
    float* out = (float*)d_out;
    int n = in_sizes[0];             // 33,554,432
    int n4 = n >> 2;                 // 8,388,608 float4s
    const int threads = 256;
    int blocks = (n4 + threads * ITEMS - 1) / (threads * ITEMS);  // 4096
    mxfp6_qdq_kernel<<<blocks, threads>>>(x, out, n4);
}